// round 12
// baseline (speedup 1.0000x reference)
#include <cuda_runtime.h>
#include <cuda_bf16.h>
#include <cstdint>

// fp8 row stride: 256 data + 32 pad = 288 B (72 words ≡ 8 mod 32 → conflict-free LDS.64 quads)
#define WSTR 288
#define XSTR 288

__device__ __align__(16) unsigned char g_W8[256 * WSTR];   // W1 * 16, e4m3, k-interleaved

static constexpr float X_SCALE  = 4096.f;
static constexpr float W_SCALE  = 16.f;
static constexpr float INV_XS   = 1.f / 4096.f;
static constexpr float SCALE_UP = 65536.f;         // X_SCALE * W_SCALE (fold into b1)
static constexpr float DESCALE  = 1.f / 65536.f;   // fold into w2

// k-interleave within each 32-chunk: LDS.64 at (chunk*32 + tg*8) returns the
// (k = tg*4..+3, k+16..+19) byte pair mma.m16n8k32 wants as a register pair.
__device__ __forceinline__ int kmap(int k) {
    int c = k >> 5, j = k & 31;
    return c * 32 + ((j >> 2) & 3) * 8 + (j >> 4) * 4 + (j & 3);
}

__global__ void convert_w_kernel(const float* __restrict__ W1) {
    int e = blockIdx.x * blockDim.x + threadIdx.x;   // 65536
    int n = e >> 8, k = e & 255;
    float v = W1[n * 256 + k] * W_SCALE;
    unsigned short h;
    asm("cvt.rn.satfinite.e4m3x2.f32 %0, %1, %2;" : "=h"(h) : "f"(0.f), "f"(v));
    g_W8[n * WSTR + kmap(k)] = (unsigned char)(h & 0xFFu);
}

// smem per CTA: W 73728 | X 32256 (112 rows) | floats 4688  = 110672 B  (2 CTAs/SM)
static constexpr int SM_X = 73728;
static constexpr int SM_F = 105984;
static constexpr int SMEM_BYTES = SM_F + 1172 * 4;   // 110672

__device__ __forceinline__ void mma_e4m3(float c[4], const uint32_t a[4], uint32_t b0, uint32_t b1) {
    asm volatile(
        "mma.sync.aligned.m16n8k32.row.col.f32.e4m3.e4m3.f32 "
        "{%0,%1,%2,%3}, {%4,%5,%6,%7}, {%8,%9}, {%0,%1,%2,%3};\n"
        : "+f"(c[0]), "+f"(c[1]), "+f"(c[2]), "+f"(c[3])
        : "r"(a[0]), "r"(a[1]), "r"(a[2]), "r"(a[3]), "r"(b0), "r"(b1));
}

__global__ __launch_bounds__(256, 2)
void nais_kernel(const int* __restrict__ history,
                 const int* __restrict__ target,
                 const int* __restrict__ hregion,
                 const int* __restrict__ tregion,
                 const float* __restrict__ tdist,
                 const float* __restrict__ E_hist,
                 const float* __restrict__ E_tgt,
                 const float* __restrict__ E_reg,
                 const float* __restrict__ E_dist,
                 const float* __restrict__ b1,
                 const float* __restrict__ w2,
                 float* __restrict__ out,
                 int B, int H, int G)
{
    extern __shared__ unsigned char smem[];
    unsigned char* Ws = smem;                      // [256][288] fp8 (k-interleaved, pre-scaled)
    unsigned char* Xs = smem + SM_X;               // [112][288] fp8
    float* fl    = (float*)(smem + SM_F);
    float* b1s   = fl;            // 256 (× SCALE_UP)
    float* w2s   = fl + 256;      // 256 (× DESCALE)
    float* sx    = fl + 512;      // 128
    float* spp   = fl + 640;      // 4 x 128  (index: nw*2+pass)
    float* redS  = fl + 1152;     // 16
    float* miscF = fl + 1168;     // 1

    const int tid  = threadIdx.x;
    const int wid  = tid >> 5;         // 0..7
    const int lane = tid & 31;

    const int bbase = blockIdx.x * G;
    if (bbase >= B) return;
    const int gcnt = min(G, B - bbase);

    // per-lane fp8 store offsets inside a row (hist half k=4l, region half k=128+4l)
    const int offH = (lane >> 3) * 32 + (lane & 3) * 8 + ((lane >> 2) & 1) * 4;
    const int offR = offH + 128;

    // ---------------- one-time staging ----------------
    {
        const uint4* src = (const uint4*)g_W8;
        uint4* dst = (uint4*)Ws;
        #pragma unroll 4
        for (int i = tid; i < 256 * WSTR / 16; i += 256) dst[i] = src[i];
        if (tid < 256) { b1s[tid] = b1[tid] * SCALE_UP; w2s[tid] = w2[tid] * DESCALE; }
        // zero rows [H,112) once (never rewritten)
        for (int i = tid; i < (112 - H) * (XSTR / 16); i += 256) {
            int r = H + i / (XSTR / 16), c = (i % (XSTR / 16)) * 16;
            *(uint4*)(Xs + r * XSTR + c) = make_uint4(0, 0, 0, 0);
        }
        if (wid == 0) {
            float v = E_dist[lane] + E_dist[lane + 32] + E_dist[lane + 64] + E_dist[lane + 96];
            #pragma unroll
            for (int o = 16; o; o >>= 1) v += __shfl_down_sync(0xffffffffu, v, o);
            if (lane == 0) miscF[0] = v;
        }
    }
    __syncthreads();
    const float distsum = miscF[0];

    // warp tiling: 4 m-warps x 2 n-warps; two n128 passes
    const int mw = wid >> 1;          // rows [32mw, 32mw+32); mw==3: rows 96..111 only
    const int nw = wid & 1;           // cols [64nw, 64nw+64) within pass half
    const int g  = lane >> 2;
    const int tg = lane & 3;
    const int r0 = mw * 32 + g;
    const bool full_m = (mw < 3);

    for (int gi = 0; gi < gcnt; ++gi) {
        const int batch = bbase + gi;
        const int tgtI  = target[batch];

        // ---------------- gather X = hist (*) tgt (fp8, pre-scaled) + fp32 row sums ----------------
        {
            const int tregI = tregion[batch];
            float4 t1 = *(const float4*)(E_tgt + (size_t)tgtI  * 128 + 4 * lane);
            float4 t2 = *(const float4*)(E_reg + (size_t)tregI * 128 + 4 * lane);
            t1.x *= X_SCALE; t1.y *= X_SCALE; t1.z *= X_SCALE; t1.w *= X_SCALE;
            t2.x *= X_SCALE; t2.y *= X_SCALE; t2.z *= X_SCALE; t2.w *= X_SCALE;
            for (int h = wid; h < H; h += 8) {
                int item = history[(size_t)batch * H + h];
                int rg   = hregion[(size_t)batch * H + h];
                float4 v1 = *(const float4*)(E_hist + (size_t)item * 128 + 4 * lane);
                float4 v2 = *(const float4*)(E_reg  + (size_t)rg   * 128 + 4 * lane);
                float x0 = v1.x * t1.x, x1 = v1.y * t1.y, x2 = v1.z * t1.z, x3 = v1.w * t1.w;
                float y0 = v2.x * t2.x, y1 = v2.y * t2.y, y2 = v2.z * t2.z, y3 = v2.w * t2.w;
                float s = (x0 + x1) + (x2 + x3) + (y0 + y1) + (y2 + y3);
                unsigned short pa, pb, pc, pd;
                asm("cvt.rn.satfinite.e4m3x2.f32 %0, %1, %2;" : "=h"(pa) : "f"(x1), "f"(x0));
                asm("cvt.rn.satfinite.e4m3x2.f32 %0, %1, %2;" : "=h"(pb) : "f"(x3), "f"(x2));
                asm("cvt.rn.satfinite.e4m3x2.f32 %0, %1, %2;" : "=h"(pc) : "f"(y1), "f"(y0));
                asm("cvt.rn.satfinite.e4m3x2.f32 %0, %1, %2;" : "=h"(pd) : "f"(y3), "f"(y2));
                *(uint32_t*)(Xs + h * XSTR + offH) = (uint32_t)pa | ((uint32_t)pb << 16);
                *(uint32_t*)(Xs + h * XSTR + offR) = (uint32_t)pc | ((uint32_t)pd << 16);
                #pragma unroll
                for (int o = 16; o; o >>= 1) s += __shfl_down_sync(0xffffffffu, s, o);
                if (lane == 0) sx[h] = s * INV_XS;
            }
        }
        __syncthreads();

        // ---------------- GEMM (fp8): two n128 passes, warp = m32 x n64 per pass ----------------
        #pragma unroll
        for (int pass = 0; pass < 2; ++pass) {
            float acc[2][8][4];
            #pragma unroll
            for (int mt = 0; mt < 2; ++mt)
                #pragma unroll
                for (int nt = 0; nt < 8; ++nt)
                    #pragma unroll
                    for (int i = 0; i < 4; ++i) acc[mt][nt][i] = 0.f;

            const unsigned char* Ar = Xs + r0 * XSTR + tg * 8;
            const unsigned char* Br = Ws + (pass * 128 + nw * 64 + g) * WSTR + tg * 8;

            #pragma unroll 2
            for (int c = 0; c < 8; ++c) {
                const int co = c * 32;
                uint32_t a[2][4];
                { uint2 t = *(const uint2*)(Ar + co);             a[0][0] = t.x; a[0][2] = t.y; }
                { uint2 t = *(const uint2*)(Ar + 8  * XSTR + co); a[0][1] = t.x; a[0][3] = t.y; }
                if (full_m) {
                    { uint2 t = *(const uint2*)(Ar + 16 * XSTR + co); a[1][0] = t.x; a[1][2] = t.y; }
                    { uint2 t = *(const uint2*)(Ar + 24 * XSTR + co); a[1][1] = t.x; a[1][3] = t.y; }
                    #pragma unroll
                    for (int nt = 0; nt < 8; ++nt) {
                        uint2 b = *(const uint2*)(Br + nt * 8 * WSTR + co);
                        mma_e4m3(acc[0][nt], a[0], b.x, b.y);
                        mma_e4m3(acc[1][nt], a[1], b.x, b.y);
                    }
                } else {
                    #pragma unroll
                    for (int nt = 0; nt < 8; ++nt) {
                        uint2 b = *(const uint2*)(Br + nt * 8 * WSTR + co);
                        mma_e4m3(acc[0][nt], a[0], b.x, b.y);
                    }
                }
            }

            // epilogue for this pass: +b1', relu, dot w2'
            float s0 = 0.f, s1 = 0.f, s2 = 0.f, s3 = 0.f;
            #pragma unroll
            for (int nt = 0; nt < 8; ++nt) {
                int k0 = pass * 128 + nw * 64 + nt * 8 + tg * 2;
                float w0 = w2s[k0], w1v = w2s[k0 + 1];
                float q0 = b1s[k0], q1 = b1s[k0 + 1];
                s0 += fmaxf(acc[0][nt][0] + q0, 0.f) * w0 + fmaxf(acc[0][nt][1] + q1, 0.f) * w1v;
                s1 += fmaxf(acc[0][nt][2] + q0, 0.f) * w0 + fmaxf(acc[0][nt][3] + q1, 0.f) * w1v;
                if (full_m) {
                    s2 += fmaxf(acc[1][nt][0] + q0, 0.f) * w0 + fmaxf(acc[1][nt][1] + q1, 0.f) * w1v;
                    s3 += fmaxf(acc[1][nt][2] + q0, 0.f) * w0 + fmaxf(acc[1][nt][3] + q1, 0.f) * w1v;
                }
            }
            s0 += __shfl_xor_sync(0xffffffffu, s0, 1); s0 += __shfl_xor_sync(0xffffffffu, s0, 2);
            s1 += __shfl_xor_sync(0xffffffffu, s1, 1); s1 += __shfl_xor_sync(0xffffffffu, s1, 2);
            if (full_m) {
                s2 += __shfl_xor_sync(0xffffffffu, s2, 1); s2 += __shfl_xor_sync(0xffffffffu, s2, 2);
                s3 += __shfl_xor_sync(0xffffffffu, s3, 1); s3 += __shfl_xor_sync(0xffffffffu, s3, 2);
            }
            if (tg == 0) {
                float* sp = spp + (nw * 2 + pass) * 128;
                sp[r0]     = s0;
                sp[r0 + 8] = s1;
                if (full_m) { sp[r0 + 16] = s2; sp[r0 + 24] = s3; }
            }
        }
        __syncthreads();

        // ---------------- masked exp, BETA=0.5 normalize, pred, sigmoid ----------------
        {
            float eS = 0.f, eP = 0.f;
            if (tid < 128 && tid < H) {
                float sc = spp[tid] + spp[128 + tid] + spp[256 + tid] + spp[384 + tid]
                         + tdist[batch] * distsum;
                float e = __expf(sc);
                if (history[(size_t)batch * H + tid] == tgtI) e = 0.f;
                eS = e; eP = e * sx[tid];
            }
            #pragma unroll
            for (int o = 16; o; o >>= 1) {
                eS += __shfl_down_sync(0xffffffffu, eS, o);
                eP += __shfl_down_sync(0xffffffffu, eP, o);
            }
            if (wid < 4 && lane == 0) { redS[wid] = eS; redS[8 + wid] = eP; }
        }
        __syncthreads();
        if (tid == 0) {
            float S = redS[0] + redS[1] + redS[2] + redS[3];
            float P = redS[8] + redS[9] + redS[10] + redS[11];
            float pred = P / sqrtf(S);     // attn = exp_A / sum^BETA, BETA=0.5
            out[batch] = 1.f / (1.f + __expf(-pred));
        }
        __syncthreads();   // protect sx / Xs / spp before next batch overwrites
    }
}

extern "C" void kernel_launch(void* const* d_in, const int* in_sizes, int n_in,
                              void* d_out, int out_size)
{
    const int*   history = (const int*)d_in[0];
    const int*   target  = (const int*)d_in[1];
    const int*   hregion = (const int*)d_in[2];
    const int*   tregion = (const int*)d_in[3];
    const float* tdist   = (const float*)d_in[4];
    const float* E_hist  = (const float*)d_in[5];
    const float* E_tgt   = (const float*)d_in[6];
    const float* E_reg   = (const float*)d_in[7];
    const float* E_dist  = (const float*)d_in[8];
    const float* W1      = (const float*)d_in[9];
    const float* b1      = (const float*)d_in[10];
    const float* w2      = (const float*)d_in[11];
    float* out = (float*)d_out;

    const int B = in_sizes[1];                 // target: [B]
    const int H = in_sizes[0] / B;             // history: [B,H]

    convert_w_kernel<<<64, 1024>>>(W1);        // W1 only, ~3us

    // 2 CTAs per SM: target 296 resident CTAs, single wave
    const int G = (B + 295) / 296;             // 7 batches per CTA for B=2048
    const int grid = (B + G - 1) / G;          // 293
    cudaFuncSetAttribute(nais_kernel, cudaFuncAttributeMaxDynamicSharedMemorySize, SMEM_BYTES);
    nais_kernel<<<grid, 256, SMEM_BYTES>>>(history, target, hregion, tregion, tdist,
                                           E_hist, E_tgt, E_reg, E_dist,
                                           b1, w2, out, B, H, G);
}